// round 2
// baseline (speedup 1.0000x reference)
#include <cuda_runtime.h>
#include <math.h>

#define NB 16
#define CELLS 4096
#define SPB 1024
#define NC 513
#define ESTRIDE 1032            // padded floats per (b,cell) spectrum row
#define MIC_CELL 2184           // 8*256 + 8*16 + 8
#define PADI(i) ((i) + ((i) >> 4))

// ---------------- scratch --------------------------------------------------
__device__ __align__(256) float g_E[(size_t)NB * CELLS * ESTRIDE];  // 270 MB, excitation spectra
__device__ float g_micF[NB][ESTRIDE];
__device__ float2 g_tw[256];       // e^{-2pi i q/512}  (mic radix-2 FFT)
__device__ float2 g_wu[NC];        // e^{-2pi i k/1024} (rfft pack/unpack)
__device__ float2 g_tw512[512];    // e^{-2pi i q/512}  (radix-8 stages)

__global__ void init_tw_kernel() {
    int t = threadIdx.x;
    if (t < 256) {
        double a = -2.0 * M_PI * (double)t / 512.0;
        g_tw[t] = make_float2((float)cos(a), (float)sin(a));
    }
    if (t < NC) {
        double a = -2.0 * M_PI * (double)t / 1024.0;
        g_wu[t] = make_float2((float)cos(a), (float)sin(a));
    }
    if (t < 512) {
        double a = -2.0 * M_PI * (double)t / 512.0;
        g_tw512[t] = make_float2((float)cos(a), (float)sin(a));
    }
}

// ---------------- complex helpers ------------------------------------------
__device__ __forceinline__ float2 cadd(float2 a, float2 b) { return make_float2(a.x+b.x, a.y+b.y); }
__device__ __forceinline__ float2 csub(float2 a, float2 b) { return make_float2(a.x-b.x, a.y-b.y); }
__device__ __forceinline__ float2 cmul(float2 a, float2 b) {
    return make_float2(a.x*b.x - a.y*b.y, a.x*b.y + a.y*b.x);
}
__device__ __forceinline__ float2 mulmi(float2 a) { return make_float2(a.y, -a.x); }  // * (-i)

// y_k = sum_j x_j * w8^{jk},  w8 = e^{-i pi/4}
__device__ __forceinline__ void dft8(const float2* x, float2* y) {
    float2 t0, t1, t2, t3;
    t0 = cadd(x[0], x[4]); t1 = csub(x[0], x[4]);
    t2 = cadd(x[2], x[6]); t3 = mulmi(csub(x[2], x[6]));
    float2 E0 = cadd(t0, t2), E1 = cadd(t1, t3), E2 = csub(t0, t2), E3 = csub(t1, t3);
    t0 = cadd(x[1], x[5]); t1 = csub(x[1], x[5]);
    t2 = cadd(x[3], x[7]); t3 = mulmi(csub(x[3], x[7]));
    float2 O0 = cadd(t0, t2), O1 = cadd(t1, t3), O2 = csub(t0, t2), O3 = csub(t1, t3);
    const float r = 0.70710678118654752f;
    float2 O1w = make_float2(r*(O1.x + O1.y), r*(O1.y - O1.x));   // *w8^1
    float2 O2w = mulmi(O2);                                        // *w8^2
    float2 O3w = make_float2(r*(O3.y - O3.x), -r*(O3.x + O3.y));  // *w8^3
    y[0] = cadd(E0, O0);  y[4] = csub(E0, O0);
    y[1] = cadd(E1, O1w); y[5] = csub(E1, O1w);
    y[2] = cadd(E2, O2w); y[6] = csub(E2, O2w);
    y[3] = cadd(E3, O3w); y[7] = csub(E3, O3w);
}

__device__ __forceinline__ float interp_env(const float* simp, int t) {
    float c = ((float)t + 0.5f) * 0.015625f - 0.5f;
    c = fminf(fmaxf(c, 0.0f), 15.0f);
    float lof = floorf(c);
    int lo = (int)lof;
    int hi = min(lo + 1, 15);
    float w = c - lof;
    float v = simp[lo] * (1.0f - w) + simp[hi] * w;
    return fminf(fmaxf(v, 0.0f), 1.0f);
}

// ---------------- K1: all 65536 excitation rFFTs (radix-8 Stockham) ---------
// 2 FFTs per 128-thread block; 64 threads per FFT, 8 points per thread.
__global__ void __launch_bounds__(128) fft_all_kernel(
    const float* __restrict__ imp, const float* __restrict__ noise)
{
    __shared__ float2 bufs[2][2][544];   // [fft][ping/pong], PADI(511)=542
    __shared__ float  simp[2][16];
    const int fi = threadIdx.x >> 6;
    const int t  = threadIdx.x & 63;
    const int b  = blockIdx.x >> 11;
    const int cell0 = (blockIdx.x & 2047) << 1;
    const size_t rowBC = (size_t)b * CELLS + cell0 + fi;

    if (threadIdx.x < 32) {
        int f = threadIdx.x >> 4, i = threadIdx.x & 15;
        simp[f][i] = imp[((size_t)b * CELLS + cell0 + f) * 16 + i];
    }
    __syncthreads();

    const float2* nrow = (const float2*)(noise + rowBC * SPB);
    float2* src = bufs[fi][0];
    float2* dst = bufs[fi][1];
#pragma unroll
    for (int j = 0; j < 8; j++) {
        int n = t + 64 * j;
        float2 nn = nrow[n];
        float e0 = interp_env(simp[fi], 2*n)     * nn.x;
        float e1 = interp_env(simp[fi], 2*n + 1) * nn.y;
        src[PADI(n)] = make_float2(e0, e1);
    }

#pragma unroll
    for (int s = 0; s < 3; s++) {
        const int m = (s == 0) ? 1 : (s == 1) ? 8 : 64;
        const int u = t & (m - 1);
        const int v = t / m;
        __syncthreads();
        float2 x[8];
#pragma unroll
        for (int j = 0; j < 8; j++) x[j] = src[PADI(t + 64 * j)];
        float2 y[8];
        dft8(x, y);
        const int e = v * m;
#pragma unroll
        for (int k = 1; k < 8; k++) y[k] = cmul(y[k], g_tw512[(k * e) & 511]);
#pragma unroll
        for (int k = 0; k < 8; k++) dst[PADI((8 * v + k) * m + u)] = y[k];
        float2* tmp = src; src = dst; dst = tmp;
    }
    __syncthreads();

    // unpack packed real FFT -> 513 bins, write E
    float2* Erow = (float2*)(g_E + rowBC * ESTRIDE);
#pragma unroll
    for (int j = 0; j < 9; j++) {
        int k = t + 64 * j;
        if (k <= 512) {
            float2 Zk = src[PADI(k & 511)];
            float2 Zm = src[PADI((512 - k) & 511)];
            float Ax = 0.5f * (Zk.x + Zm.x);
            float Ay = 0.5f * (Zk.y - Zm.y);
            float Bx = 0.5f * (Zk.x - Zm.x);
            float By = 0.5f * (Zk.y + Zm.y);
            float2 W = g_wu[k];
            float wbx = W.x * Bx - W.y * By;
            float wby = W.x * By + W.y * Bx;
            Erow[k] = make_float2(Ax + wby, Ay - wbx);   // X = A - i*(W*B)
        }
    }
}

// ---------------- K2: whole 16-step scan, state in smem ---------------------
// Each block owns 4 float lanes (2 complex bins) for ALL 4096 cells.
// smem layout: T[f*4352 + x*272 + y*17 + z]  (bank-conflict-free box passes)
#define SPF 4352
#define SPX 272
#define SPY 17
__global__ void __launch_bounds__(512) scan_kernel(const float* __restrict__ tf) {
    extern __shared__ float T[];   // 4*4352 floats = 69632 B
    const int tid  = threadIdx.x;
    const int base = blockIdx.x * 4;
    const int k0 = min(base >> 1, 512);
    const int k1 = min((base >> 1) + 1, 512);

    for (int i = tid; i < 4 * SPF; i += 512) T[i] = 0.0f;
    __syncthreads();

    for (int b = 0; b < NB; b++) {
        const float* Eb = g_E + (size_t)b * CELLS * ESTRIDE + base;
        const float* tb = tf + (size_t)b * CELLS * NC;

        // V = clip(tf) * (S + E); tap mic before box
        for (int c = tid; c < CELLS; c += 512) {
            float4 Ev = *(const float4*)(Eb + (size_t)c * ESTRIDE);
            const float* trow = tb + (size_t)c * NC;
            float r0 = fminf(fmaxf(__ldg(trow + k0), 0.0f), 1.0f);
            float r1 = fminf(fmaxf(__ldg(trow + k1), 0.0f), 1.0f);
            int x = c >> 8, y = (c >> 4) & 15, z = c & 15;
            int sa = x * SPX + y * SPY + z;
            float v0 = r0 * (T[sa]           + Ev.x);
            float v1 = r0 * (T[sa + SPF]     + Ev.y);
            float v2 = r1 * (T[sa + 2*SPF]   + Ev.z);
            float v3 = r1 * (T[sa + 3*SPF]   + Ev.w);
            T[sa] = v0; T[sa + SPF] = v1; T[sa + 2*SPF] = v2; T[sa + 3*SPF] = v3;
            if (c == MIC_CELL) {
                g_micF[b][base + 0] = v0; g_micF[b][base + 1] = v1;
                g_micF[b][base + 2] = v2; g_micF[b][base + 3] = v3;
            }
        }
        __syncthreads();

        // X pass (stride SPX)
        for (int l = tid; l < 1024; l += 512) {
            int f = l >> 8, yz = l & 255;
            int off = f * SPF + (yz >> 4) * SPY + (yz & 15);
            float v[16];
#pragma unroll
            for (int x = 0; x < 16; x++) v[x] = T[off + x * SPX];
#pragma unroll
            for (int x = 0; x < 16; x++) {
                float s = v[x];
                if (x > 0)  s += v[x - 1];
                if (x < 15) s += v[x + 1];
                T[off + x * SPX] = s;
            }
        }
        __syncthreads();

        // Y pass (stride SPY)
        for (int l = tid; l < 1024; l += 512) {
            int f = l >> 8, xz = l & 255;
            int off = f * SPF + (xz >> 4) * SPX + (xz & 15);
            float v[16];
#pragma unroll
            for (int y = 0; y < 16; y++) v[y] = T[off + y * SPY];
#pragma unroll
            for (int y = 0; y < 16; y++) {
                float s = v[y];
                if (y > 0)  s += v[y - 1];
                if (y < 15) s += v[y + 1];
                T[off + y * SPY] = s;
            }
        }
        __syncthreads();

        // Z pass (stride 1)
        for (int l = tid; l < 1024; l += 512) {
            int f = l >> 8, xy = l & 255;
            int off = f * SPF + (xy >> 4) * SPX + (xy & 15) * SPY;
            float v[16];
#pragma unroll
            for (int z = 0; z < 16; z++) v[z] = T[off + z];
#pragma unroll
            for (int z = 0; z < 16; z++) {
                float s = v[z];
                if (z > 0)  s += v[z - 1];
                if (z < 15) s += v[z + 1];
                T[off + z] = s;
            }
        }
        __syncthreads();
    }
}

// ---------------- radix-2 FFT for the 16 tiny mic inverse transforms --------
__device__ __forceinline__ float2* fft512_r2(float2* a, float2* b, int tid) {
    __syncthreads();
    float2* src = a;
    float2* dst = b;
#pragma unroll
    for (int s = 0; s < 9; s++) {
        int m  = 1 << s;
        int jm = tid & ~(m - 1);
        float2 x0 = src[tid];
        float2 x1 = src[tid + 256];
        float2 w  = g_tw[jm];
        float sx = x0.x + x1.x, sy = x0.y + x1.y;
        float dx = x0.x - x1.x, dy = x0.y - x1.y;
        dst[tid + jm]     = make_float2(sx, sy);
        dst[tid + jm + m] = make_float2(w.x*dx - w.y*dy, w.x*dy + w.y*dx);
        __syncthreads();
        float2* t = src; src = dst; dst = t;
    }
    return src;
}

__global__ void __launch_bounds__(256) mic_kernel(float* __restrict__ out) {
    __shared__ float2 bufA[512];
    __shared__ float2 bufB[512];
    int b   = blockIdx.x;
    int tid = threadIdx.x;
    const float* M = g_micF[b];

    for (int k = tid; k < 512; k += 256) {
        float2 Xk = make_float2(M[2 * k], M[2 * k + 1]);
        int mk = 512 - k;
        float2 Xm = make_float2(M[2 * mk], M[2 * mk + 1]);
        float Ax = 0.5f * (Xk.x + Xm.x);
        float Ay = 0.5f * (Xk.y - Xm.y);
        float Dx = 0.5f * (Xk.x - Xm.x);
        float Dy = 0.5f * (Xk.y + Xm.y);
        float2 W = g_wu[k];
        float cx = W.x * Dx + W.y * Dy;
        float cy = W.x * Dy - W.y * Dx;
        bufA[k] = make_float2(Ax - cy, -(Ay + cx));
    }

    float2* Zr = fft512_r2(bufA, bufB, tid);

    const float s = 1.0f / 512.0f;
    for (int n = tid; n < 512; n += 256) {
        float2 z = Zr[n];
        out[b * 1024 + 2 * n]     =  z.x * s;
        out[b * 1024 + 2 * n + 1] = -z.y * s;
    }
}

// ---------------- launch ----------------------------------------------------
extern "C" void kernel_launch(void* const* d_in, const int* in_sizes, int n_in,
                              void* d_out, int out_size) {
    const float* tf = nullptr;
    const float* imp = nullptr;
    const float* noise = nullptr;
    for (int i = 0; i < n_in; i++) {
        if      (in_sizes[i] == 33619968) tf    = (const float*)d_in[i];
        else if (in_sizes[i] == 1048576)  imp   = (const float*)d_in[i];
        else if (in_sizes[i] == 67108864) noise = (const float*)d_in[i];
    }

    init_tw_kernel<<<1, 544>>>();

    fft_all_kernel<<<NB * 2048, 128>>>(imp, noise);

    cudaFuncSetAttribute(scan_kernel, cudaFuncAttributeMaxDynamicSharedMemorySize,
                         4 * SPF * (int)sizeof(float));
    scan_kernel<<<257, 512, 4 * SPF * sizeof(float)>>>(tf);

    mic_kernel<<<NB, 256>>>((float*)d_out);
}

// round 3
// speedup vs baseline: 1.8375x; 1.8375x over previous
#include <cuda_runtime.h>
#include <math.h>

#define NB 16
#define CELLS 4096
#define SPB 1024
#define NC 513
#define ESTRIDE 1032            // floats per cell row; 4128 B = 129 * 32 B (sector aligned)
#define MIC_CELL 2184           // 8*256 + 8*16 + 8
#define PADI(i) ((i) + ((i) >> 4))

// ---------------- scratch --------------------------------------------------
__device__ __align__(256) float g_S[(size_t)CELLS * ESTRIDE];   // state spectra
__device__ __align__(256) float g_V[(size_t)CELLS * ESTRIDE];   // pre-box spectra
__device__ float g_micF[NB][ESTRIDE];
__device__ float2 g_tw[256];       // e^{-2pi i q/512}  (mic radix-2 FFT)
__device__ float2 g_wu[NC];        // e^{-2pi i k/1024} (rfft pack/unpack)
__device__ float2 g_tw512[512];    // e^{-2pi i q/512}  (radix-8 stages)

__global__ void init_tw_kernel() {
    int t = threadIdx.x;
    if (t < 256) {
        double a = -2.0 * M_PI * (double)t / 512.0;
        g_tw[t] = make_float2((float)cos(a), (float)sin(a));
    }
    if (t < NC) {
        double a = -2.0 * M_PI * (double)t / 1024.0;
        g_wu[t] = make_float2((float)cos(a), (float)sin(a));
    }
    if (t < 512) {
        double a = -2.0 * M_PI * (double)t / 512.0;
        g_tw512[t] = make_float2((float)cos(a), (float)sin(a));
    }
}

// ---------------- complex helpers ------------------------------------------
__device__ __forceinline__ float2 cadd(float2 a, float2 b) { return make_float2(a.x+b.x, a.y+b.y); }
__device__ __forceinline__ float2 csub(float2 a, float2 b) { return make_float2(a.x-b.x, a.y-b.y); }
__device__ __forceinline__ float2 cmul(float2 a, float2 b) {
    return make_float2(a.x*b.x - a.y*b.y, a.x*b.y + a.y*b.x);
}
__device__ __forceinline__ float2 mulmi(float2 a) { return make_float2(a.y, -a.x); }  // * (-i)

__device__ __forceinline__ void dft8(const float2* x, float2* y) {
    float2 t0, t1, t2, t3;
    t0 = cadd(x[0], x[4]); t1 = csub(x[0], x[4]);
    t2 = cadd(x[2], x[6]); t3 = mulmi(csub(x[2], x[6]));
    float2 E0 = cadd(t0, t2), E1 = cadd(t1, t3), E2 = csub(t0, t2), E3 = csub(t1, t3);
    t0 = cadd(x[1], x[5]); t1 = csub(x[1], x[5]);
    t2 = cadd(x[3], x[7]); t3 = mulmi(csub(x[3], x[7]));
    float2 O0 = cadd(t0, t2), O1 = cadd(t1, t3), O2 = csub(t0, t2), O3 = csub(t1, t3);
    const float r = 0.70710678118654752f;
    float2 O1w = make_float2(r*(O1.x + O1.y), r*(O1.y - O1.x));   // *w8^1
    float2 O2w = mulmi(O2);                                        // *w8^2
    float2 O3w = make_float2(r*(O3.y - O3.x), -r*(O3.x + O3.y));  // *w8^3
    y[0] = cadd(E0, O0);  y[4] = csub(E0, O0);
    y[1] = cadd(E1, O1w); y[5] = csub(E1, O1w);
    y[2] = cadd(E2, O2w); y[6] = csub(E2, O2w);
    y[3] = cadd(E3, O3w); y[7] = csub(E3, O3w);
}

__device__ __forceinline__ float interp_env(const float* simp, int t) {
    float c = ((float)t + 0.5f) * 0.015625f - 0.5f;
    c = fminf(fmaxf(c, 0.0f), 15.0f);
    float lof = floorf(c);
    int lo = (int)lof;
    int hi = min(lo + 1, 15);
    float w = c - lof;
    float v = simp[lo] * (1.0f - w) + simp[hi] * w;
    return fminf(fmaxf(v, 0.0f), 1.0f);
}

// ---------------- K1: per-step env rFFT + V = clip(tf)*(S+E) ----------------
// 2 FFTs per 128-thread block; 64 threads per FFT, 8 points per thread.
__global__ void __launch_bounds__(128) step_kernel(
    const float* __restrict__ tf,
    const float* __restrict__ imp,
    const float* __restrict__ noise,
    int b)
{
    __shared__ float2 bufs[2][2][544];   // [fft][ping/pong], PADI(511)=542
    __shared__ float  simp[2][16];
    const int fi = threadIdx.x >> 6;
    const int t  = threadIdx.x & 63;
    const int cell0 = blockIdx.x << 1;
    const int cell  = cell0 + fi;
    const size_t rowBC = (size_t)b * CELLS + cell;

    if (threadIdx.x < 32) {
        int f = threadIdx.x >> 4, i = threadIdx.x & 15;
        simp[f][i] = imp[((size_t)b * CELLS + cell0 + f) * 16 + i];
    }
    __syncthreads();

    const float2* nrow = (const float2*)(noise + rowBC * SPB);
    float2* src = bufs[fi][0];
    float2* dst = bufs[fi][1];
#pragma unroll
    for (int j = 0; j < 8; j++) {
        int n = t + 64 * j;
        float2 nn = nrow[n];
        float e0 = interp_env(simp[fi], 2*n)     * nn.x;
        float e1 = interp_env(simp[fi], 2*n + 1) * nn.y;
        src[PADI(n)] = make_float2(e0, e1);
    }

#pragma unroll
    for (int s = 0; s < 3; s++) {
        const int m = (s == 0) ? 1 : (s == 1) ? 8 : 64;
        const int u = t & (m - 1);
        const int v = t / m;
        __syncthreads();
        float2 x[8];
#pragma unroll
        for (int j = 0; j < 8; j++) x[j] = src[PADI(t + 64 * j)];
        float2 y[8];
        dft8(x, y);
        const int e = v * m;
#pragma unroll
        for (int k = 1; k < 8; k++) y[k] = cmul(y[k], g_tw512[(k * e) & 511]);
#pragma unroll
        for (int k = 0; k < 8; k++) dst[PADI((8 * v + k) * m + u)] = y[k];
        float2* tmp = src; src = dst; dst = tmp;
    }
    __syncthreads();

    // unpack real-FFT bins, combine with state, apply filter, write V
    const float*  trow = tf + rowBC * (size_t)NC;
    const float2* Srow = (const float2*)(g_S + (size_t)cell * ESTRIDE);
    float2*       Vrow = (float2*)(g_V + (size_t)cell * ESTRIDE);
    const bool isMic = (cell == MIC_CELL);
#pragma unroll
    for (int j = 0; j < 9; j++) {
        int k = t + 64 * j;
        if (k <= 512) {
            float2 Zk = src[PADI(k & 511)];
            float2 Zm = src[PADI((512 - k) & 511)];
            float Ax = 0.5f * (Zk.x + Zm.x);
            float Ay = 0.5f * (Zk.y - Zm.y);
            float Bx = 0.5f * (Zk.x - Zm.x);
            float By = 0.5f * (Zk.y + Zm.y);
            float2 W = g_wu[k];
            float wbx = W.x * Bx - W.y * By;
            float wby = W.x * By + W.y * Bx;
            float Ex = Ax + wby;             // X = A - i*(W*B)
            float Ey = Ay - wbx;
            float r = fminf(fmaxf(trow[k], 0.0f), 1.0f);
            float2 Sv = Srow[k];
            float vx = r * (Sv.x + Ex);
            float vy = r * (Sv.y + Ey);
            Vrow[k] = make_float2(vx, vy);
            if (isMic) {
                g_micF[b][2 * k]     = vx;
                g_micF[b][2 * k + 1] = vy;
            }
        }
    }
}

// ---------------- K2: separable 3x3x3 box sum, V -> S -----------------------
// Each block owns 8 float lanes (32 B, sector-aligned) for ALL 4096 cells.
// smem layout: T[f*SPF + x*SPX + y*SPY + z]   (conflict-free line passes)
#define SPF 4353
#define SPX 272
#define SPY 17
__global__ void __launch_bounds__(1024) box_kernel() {
    extern __shared__ float T[];   // 8*4353 floats = 139,296 B
    const int tid  = threadIdx.x;
    const int base = blockIdx.x * 8;   // multiple of 32 B within a row

    // load: paired float4 -> exact 32 B sectors
#pragma unroll
    for (int it = 0; it < 8; it++) {
        int i = tid + 1024 * it;          // i in [0, 8192)
        int c = i >> 1, part = i & 1;
        float4 v = *(const float4*)(g_V + (size_t)c * ESTRIDE + base + part * 4);
        int sa = (c >> 8) * SPX + ((c >> 4) & 15) * SPY + (c & 15);
        T[(part * 4 + 0) * SPF + sa] = v.x;
        T[(part * 4 + 1) * SPF + sa] = v.y;
        T[(part * 4 + 2) * SPF + sa] = v.z;
        T[(part * 4 + 3) * SPF + sa] = v.w;
    }
    __syncthreads();

    // X pass (stride SPX): l = f*256 + y*16 + z
#pragma unroll
    for (int it = 0; it < 2; it++) {
        int l = tid + 1024 * it;
        int f = l >> 8, yz = l & 255;
        int off = f * SPF + (yz >> 4) * SPY + (yz & 15);
        float v[16];
#pragma unroll
        for (int x = 0; x < 16; x++) v[x] = T[off + x * SPX];
#pragma unroll
        for (int x = 0; x < 16; x++) {
            float s = v[x];
            if (x > 0)  s += v[x - 1];
            if (x < 15) s += v[x + 1];
            T[off + x * SPX] = s;
        }
    }
    __syncthreads();

    // Y pass (stride SPY): l = f*256 + x*16 + z
#pragma unroll
    for (int it = 0; it < 2; it++) {
        int l = tid + 1024 * it;
        int f = l >> 8, xz = l & 255;
        int off = f * SPF + (xz >> 4) * SPX + (xz & 15);
        float v[16];
#pragma unroll
        for (int y = 0; y < 16; y++) v[y] = T[off + y * SPY];
#pragma unroll
        for (int y = 0; y < 16; y++) {
            float s = v[y];
            if (y > 0)  s += v[y - 1];
            if (y < 15) s += v[y + 1];
            T[off + y * SPY] = s;
        }
    }
    __syncthreads();

    // Z pass (stride 1): l = f*256 + x*16 + y
#pragma unroll
    for (int it = 0; it < 2; it++) {
        int l = tid + 1024 * it;
        int f = l >> 8, xy = l & 255;
        int off = f * SPF + (xy >> 4) * SPX + (xy & 15) * SPY;
        float v[16];
#pragma unroll
        for (int z = 0; z < 16; z++) v[z] = T[off + z];
#pragma unroll
        for (int z = 0; z < 16; z++) {
            float s = v[z];
            if (z > 0)  s += v[z - 1];
            if (z < 15) s += v[z + 1];
            T[off + z] = s;
        }
    }
    __syncthreads();

    // store back, sector-exact
#pragma unroll
    for (int it = 0; it < 8; it++) {
        int i = tid + 1024 * it;
        int c = i >> 1, part = i & 1;
        int sa = (c >> 8) * SPX + ((c >> 4) & 15) * SPY + (c & 15);
        float4 v;
        v.x = T[(part * 4 + 0) * SPF + sa];
        v.y = T[(part * 4 + 1) * SPF + sa];
        v.z = T[(part * 4 + 2) * SPF + sa];
        v.w = T[(part * 4 + 3) * SPF + sa];
        *(float4*)(g_S + (size_t)c * ESTRIDE + base + part * 4) = v;
    }
}

// ---------------- radix-2 FFT for the 16 tiny mic inverse transforms --------
__device__ __forceinline__ float2* fft512_r2(float2* a, float2* b, int tid) {
    __syncthreads();
    float2* src = a;
    float2* dst = b;
#pragma unroll
    for (int s = 0; s < 9; s++) {
        int m  = 1 << s;
        int jm = tid & ~(m - 1);
        float2 x0 = src[tid];
        float2 x1 = src[tid + 256];
        float2 w  = g_tw[jm];
        float sx = x0.x + x1.x, sy = x0.y + x1.y;
        float dx = x0.x - x1.x, dy = x0.y - x1.y;
        dst[tid + jm]     = make_float2(sx, sy);
        dst[tid + jm + m] = make_float2(w.x*dx - w.y*dy, w.x*dy + w.y*dx);
        __syncthreads();
        float2* t = src; src = dst; dst = t;
    }
    return src;
}

__global__ void __launch_bounds__(256) mic_kernel(float* __restrict__ out) {
    __shared__ float2 bufA[512];
    __shared__ float2 bufB[512];
    int b   = blockIdx.x;
    int tid = threadIdx.x;
    const float* M = g_micF[b];

    for (int k = tid; k < 512; k += 256) {
        float2 Xk = make_float2(M[2 * k], M[2 * k + 1]);
        int mk = 512 - k;
        float2 Xm = make_float2(M[2 * mk], M[2 * mk + 1]);
        float Ax = 0.5f * (Xk.x + Xm.x);
        float Ay = 0.5f * (Xk.y - Xm.y);
        float Dx = 0.5f * (Xk.x - Xm.x);
        float Dy = 0.5f * (Xk.y + Xm.y);
        float2 W = g_wu[k];
        float cx = W.x * Dx + W.y * Dy;
        float cy = W.x * Dy - W.y * Dx;
        bufA[k] = make_float2(Ax - cy, -(Ay + cx));
    }

    float2* Zr = fft512_r2(bufA, bufB, tid);

    const float s = 1.0f / 512.0f;
    for (int n = tid; n < 512; n += 256) {
        float2 z = Zr[n];
        out[b * 1024 + 2 * n]     =  z.x * s;
        out[b * 1024 + 2 * n + 1] = -z.y * s;
    }
}

// ---------------- launch ----------------------------------------------------
extern "C" void kernel_launch(void* const* d_in, const int* in_sizes, int n_in,
                              void* d_out, int out_size) {
    const float* tf = nullptr;
    const float* imp = nullptr;
    const float* noise = nullptr;
    for (int i = 0; i < n_in; i++) {
        if      (in_sizes[i] == 33619968) tf    = (const float*)d_in[i];
        else if (in_sizes[i] == 1048576)  imp   = (const float*)d_in[i];
        else if (in_sizes[i] == 67108864) noise = (const float*)d_in[i];
    }

    void* sptr = nullptr;
    cudaGetSymbolAddress(&sptr, g_S);
    cudaMemsetAsync(sptr, 0, sizeof(float) * (size_t)CELLS * ESTRIDE);

    init_tw_kernel<<<1, 544>>>();

    cudaFuncSetAttribute(box_kernel, cudaFuncAttributeMaxDynamicSharedMemorySize,
                         8 * SPF * (int)sizeof(float));

    for (int b = 0; b < NB; b++) {
        step_kernel<<<CELLS / 2, 128>>>(tf, imp, noise, b);
        box_kernel<<<ESTRIDE / 8, 1024, 8 * SPF * sizeof(float)>>>();
    }

    mic_kernel<<<NB, 256>>>((float*)d_out);
}